// round 14
// baseline (speedup 1.0000x reference)
#include <cuda_runtime.h>
#include <cuda_bf16.h>
#include <math.h>

#define TOK 2048
#define DIM 1024
#define TDIM 3072
#define SEQ 512
#define NHEAD 16
#define HDIM 64
#define NEXP 8
#define HID 1792
#define SLOTS 4096
#define ATS 72   // attention smem stride: 72 % 32 == 8 -> conflict-free fragment LDS

// ------------------------- scratch (device globals) -------------------------
__device__ float g_xn1[TOK * DIM];
__device__ float g_qkv[TOK * TDIM];
__device__ float g_attn[TOK * DIM];
__device__ float g_x1[TOK * DIM];
__device__ float g_xn2[TOK * DIM];
__device__ float g_gbuf[SLOTS * HID];
__device__ float g_ubuf[SLOTS * HID];
__device__ float g_dbuf[SLOTS * DIM];
__device__ float g_cw[TOK * 2];
__device__ int   g_topk[TOK * 2];
__device__ int   g_slot[TOK * 2];
__device__ int   g_perm[SLOTS];
__device__ int   g_cnt[NEXP];
__device__ int   g_off[NEXP];
__device__ int   g_fill[NEXP];
__device__ float g_dist[NEXP];
__device__ float g_cs[SEQ * 32 * 2];   // rope cos/sin table

// ------------------------- small helpers -------------------------
__device__ __forceinline__ float block_sum(float v) {
    __shared__ float red[8];
    #pragma unroll
    for (int o = 16; o; o >>= 1) v += __shfl_xor_sync(0xffffffffu, v, o);
    int w = threadIdx.x >> 5;
    if ((threadIdx.x & 31) == 0) red[w] = v;
    __syncthreads();
    if (threadIdx.x < 32) {
        float t = (threadIdx.x < 8) ? red[threadIdx.x] : 0.f;
        #pragma unroll
        for (int o = 4; o; o >>= 1) t += __shfl_xor_sync(0xffffffffu, t, o);
        if (threadIdx.x == 0) red[0] = t;
    }
    __syncthreads();
    float r = red[0];
    __syncthreads();
    return r;
}

__device__ __forceinline__ unsigned f2tf32(float x) {
    unsigned r;
    asm("cvt.rna.tf32.f32 %0, %1;" : "=r"(r) : "f"(x));
    return r;
}

__device__ __forceinline__ void mma_tf32(float* c, unsigned a0, unsigned a1,
                                         unsigned a2, unsigned a3,
                                         unsigned b0, unsigned b1) {
    asm volatile(
        "mma.sync.aligned.m16n8k8.row.col.f32.tf32.tf32.f32 "
        "{%0,%1,%2,%3}, {%4,%5,%6,%7}, {%8,%9}, {%0,%1,%2,%3};"
        : "+f"(c[0]), "+f"(c[1]), "+f"(c[2]), "+f"(c[3])
        : "r"(a0), "r"(a1), "r"(a2), "r"(a3), "r"(b0), "r"(b1));
}

__device__ __forceinline__ float2 hilo(float x) {
    float h = __uint_as_float(f2tf32(x));
    return make_float2(h, __uint_as_float(f2tf32(x - h)));
}

// ------------------------- LayerNorm -------------------------
__global__ void ln_k(const float* __restrict__ x, const float* __restrict__ g,
                     const float* __restrict__ b, float* __restrict__ y) {
    int row = blockIdx.x;
    int tid = threadIdx.x;
    const float* xr = x + (size_t)row * DIM;
    float v[4];
    float s = 0.f;
    #pragma unroll
    for (int i = 0; i < 4; i++) { v[i] = xr[tid + 256 * i]; s += v[i]; }
    float mu = block_sum(s) * (1.f / 1024.f);
    float q = 0.f;
    #pragma unroll
    for (int i = 0; i < 4; i++) { float d = v[i] - mu; q += d * d; }
    float var = block_sum(q) * (1.f / 1024.f);
    float rs = rsqrtf(var + 1e-5f);
    float* yr = y + (size_t)row * DIM;
    #pragma unroll
    for (int i = 0; i < 4; i++) {
        int c = tid + 256 * i;
        yr[c] = (v[i] - mu) * rs * g[c] + b[c];
    }
}

// ------------------------- dense 3xTF32 GEMM, k-paired float2 smem -------------------------
// Row kk of Ap/Bp holds the value pair (k, k+4): kk 0-3 -> k (0..3, 4..7); kk 4-7 -> (8..11, 12..15).
// Fragment pairs (a0,a2),(a1,a3),(b0,b1) each become one LDS.64. hilo at fragment load.
__global__ void __launch_bounds__(256, 2)
gemm3x_k(const float* __restrict__ A, const float* __restrict__ B,
         float* __restrict__ C, const float* __restrict__ R, int N, int K) {
    const int bn = blockIdx.x, bm = blockIdx.y;
    __shared__ float2 Ap[8][132];
    __shared__ float2 Bp[8][132];

    const int tid = threadIdx.x;
    const int warp = tid >> 5, lane = tid & 31;
    const int g = lane >> 2, t = lane & 3;
    const int wm = (warp & 3) * 32;
    const int wn = (warp >> 2) * 64;

    // fill decomposition: fm = column (m for A, n for B), fh = k-half (0: k 0-7, 1: k 8-15)
    const int fm = tid & 127;
    const int fh = tid >> 7;
    const float* fap = A + (size_t)(bm * 128 + fm) * K + fh * 8;
    const float* fbp = B + (size_t)(fh * 8) * N + bn * 128 + fm;

    float c[2][8][4];
    #pragma unroll
    for (int im = 0; im < 2; im++)
        #pragma unroll
        for (int jn = 0; jn < 8; jn++)
            #pragma unroll
            for (int q = 0; q < 4; q++) c[im][jn][q] = 0.f;

    float4 pa0, pa1;
    float pbv[8];
    // preload tile 0
    pa0 = *(const float4*)(fap);
    pa1 = *(const float4*)(fap + 4);
    #pragma unroll
    for (int j = 0; j < 8; j++) pbv[j] = fbp[(size_t)j * N];
    {
        float a0v[4] = {pa0.x, pa0.y, pa0.z, pa0.w};
        float a1v[4] = {pa1.x, pa1.y, pa1.z, pa1.w};
        #pragma unroll
        for (int q = 0; q < 4; q++) {
            Ap[fh * 4 + q][fm] = make_float2(a0v[q], a1v[q]);
            Bp[fh * 4 + q][fm] = make_float2(pbv[q], pbv[q + 4]);
        }
    }
    __syncthreads();

    const int ntiles = K / 16;
    for (int kt = 0; kt < ntiles; kt++) {
        const bool have_next = (kt + 1) < ntiles;
        if (have_next) {
            pa0 = *(const float4*)(fap + (kt + 1) * 16);
            pa1 = *(const float4*)(fap + (kt + 1) * 16 + 4);
            #pragma unroll
            for (int j = 0; j < 8; j++)
                pbv[j] = fbp[(size_t)((kt + 1) * 16 + j) * N];
        }
        #pragma unroll
        for (int ks = 0; ks < 16; ks += 8) {
            const int kr = ks >> 1;   // 0 or 4
            unsigned ah[2][4], al[2][4];
            #pragma unroll
            for (int im = 0; im < 2; im++) {
                int m0 = wm + im * 16 + g;
                float2 v02 = Ap[kr + t][m0];
                float2 v13 = Ap[kr + t][m0 + 8];
                float2 hl;
                hl = hilo(v02.x); ah[im][0] = __float_as_uint(hl.x); al[im][0] = __float_as_uint(hl.y);
                hl = hilo(v13.x); ah[im][1] = __float_as_uint(hl.x); al[im][1] = __float_as_uint(hl.y);
                hl = hilo(v02.y); ah[im][2] = __float_as_uint(hl.x); al[im][2] = __float_as_uint(hl.y);
                hl = hilo(v13.y); ah[im][3] = __float_as_uint(hl.x); al[im][3] = __float_as_uint(hl.y);
            }
            #pragma unroll
            for (int jn = 0; jn < 8; jn++) {
                int n0 = wn + jn * 8 + g;
                float2 braw = Bp[kr + t][n0];
                float2 b0 = hilo(braw.x);
                float2 b1 = hilo(braw.y);
                unsigned bh0 = __float_as_uint(b0.x), bl0 = __float_as_uint(b0.y);
                unsigned bh1 = __float_as_uint(b1.x), bl1 = __float_as_uint(b1.y);
                #pragma unroll
                for (int im = 0; im < 2; im++) {
                    mma_tf32(c[im][jn], ah[im][0], ah[im][1], ah[im][2], ah[im][3], bl0, bl1);
                    mma_tf32(c[im][jn], al[im][0], al[im][1], al[im][2], al[im][3], bh0, bh1);
                    mma_tf32(c[im][jn], ah[im][0], ah[im][1], ah[im][2], ah[im][3], bh0, bh1);
                }
            }
        }
        if (have_next) {
            __syncthreads();
            float a0v[4] = {pa0.x, pa0.y, pa0.z, pa0.w};
            float a1v[4] = {pa1.x, pa1.y, pa1.z, pa1.w};
            #pragma unroll
            for (int q = 0; q < 4; q++) {
                Ap[fh * 4 + q][fm] = make_float2(a0v[q], a1v[q]);
                Bp[fh * 4 + q][fm] = make_float2(pbv[q], pbv[q + 4]);
            }
            __syncthreads();
        }
    }

    #pragma unroll
    for (int im = 0; im < 2; im++) {
        #pragma unroll
        for (int half = 0; half < 2; half++) {
            int row = bm * 128 + wm + im * 16 + g + half * 8;
            float* Cp = C + (size_t)row * N + bn * 128 + wn;
            if (R) {
                const float* Rp = R + (size_t)row * N + bn * 128 + wn;
                #pragma unroll
                for (int jn = 0; jn < 8; jn++) {
                    Cp[jn * 8 + 2 * t]     = c[im][jn][half * 2 + 0] + Rp[jn * 8 + 2 * t];
                    Cp[jn * 8 + 2 * t + 1] = c[im][jn][half * 2 + 1] + Rp[jn * 8 + 2 * t + 1];
                }
            } else {
                #pragma unroll
                for (int jn = 0; jn < 8; jn++) {
                    Cp[jn * 8 + 2 * t]     = c[im][jn][half * 2 + 0];
                    Cp[jn * 8 + 2 * t + 1] = c[im][jn][half * 2 + 1];
                }
            }
        }
    }
}

// ------------------------- MoE grouped GEMM, TF32, k-paired float2 smem -------------------------
__global__ void __launch_bounds__(256, 2)
moe_mma_k(const float* __restrict__ X, const float* __restrict__ W,
          float* __restrict__ Cb, int K, int N, int gather) {
    const int e = blockIdx.z;
    const int cnt = g_cnt[e];
    const int bm = blockIdx.y;
    if (bm * 128 >= cnt) return;
    const int off = g_off[e];
    const int bn = blockIdx.x;
    const float* B = W + (size_t)e * K * N;
    float* C = Cb + (size_t)off * N;

    __shared__ float2 Ap[2][8][132];
    __shared__ float2 Bp[2][8][132];

    const int tid = threadIdx.x;
    const int warp = tid >> 5, lane = tid & 31;
    const int g = lane >> 2, t = lane & 3;
    const int wm = (warp & 3) * 32;
    const int wn = (warp >> 2) * 64;

    // fill decomposition
    const int fm = tid & 127;
    const int fh = tid >> 7;
    const bool favA = (bm * 128 + fm) < cnt;
    int slotA = off + bm * 128 + (favA ? fm : 0);
    int srcA = gather ? g_perm[slotA] : slotA;
    const float* fap = X + (size_t)srcA * K + fh * 8;
    const float* fbp = B + (size_t)(fh * 8) * N + bn * 128 + fm;

    float c[2][8][4];
    #pragma unroll
    for (int im = 0; im < 2; im++)
        #pragma unroll
        for (int jn = 0; jn < 8; jn++)
            #pragma unroll
            for (int q = 0; q < 4; q++) c[im][jn][q] = 0.f;

    const int ntiles = K / 16;

    float4 pa0, pa1;
    float pbv[8];
    pa0 = favA ? *(const float4*)(fap)     : make_float4(0.f, 0.f, 0.f, 0.f);
    pa1 = favA ? *(const float4*)(fap + 4) : make_float4(0.f, 0.f, 0.f, 0.f);
    #pragma unroll
    for (int j = 0; j < 8; j++) pbv[j] = fbp[(size_t)j * N];
    {
        float a0v[4] = {pa0.x, pa0.y, pa0.z, pa0.w};
        float a1v[4] = {pa1.x, pa1.y, pa1.z, pa1.w};
        #pragma unroll
        for (int q = 0; q < 4; q++) {
            Ap[0][fh * 4 + q][fm] = make_float2(__uint_as_float(f2tf32(a0v[q])),
                                                __uint_as_float(f2tf32(a1v[q])));
            Bp[0][fh * 4 + q][fm] = make_float2(__uint_as_float(f2tf32(pbv[q])),
                                                __uint_as_float(f2tf32(pbv[q + 4])));
        }
    }
    __syncthreads();

    int cur = 0;
    for (int kt = 0; kt < ntiles; kt++) {
        const bool have_next = (kt + 1) < ntiles;
        if (have_next) {
            pa0 = favA ? *(const float4*)(fap + (kt + 1) * 16)
                       : make_float4(0.f, 0.f, 0.f, 0.f);
            pa1 = favA ? *(const float4*)(fap + (kt + 1) * 16 + 4)
                       : make_float4(0.f, 0.f, 0.f, 0.f);
            #pragma unroll
            for (int j = 0; j < 8; j++)
                pbv[j] = fbp[(size_t)((kt + 1) * 16 + j) * N];
        }
        #pragma unroll
        for (int ks = 0; ks < 16; ks += 8) {
            const int kr = ks >> 1;
            unsigned a0[2], a1[2], a2[2], a3[2];
            #pragma unroll
            for (int im = 0; im < 2; im++) {
                int m0 = wm + im * 16 + g;
                float2 v02 = Ap[cur][kr + t][m0];
                float2 v13 = Ap[cur][kr + t][m0 + 8];
                a0[im] = __float_as_uint(v02.x);
                a1[im] = __float_as_uint(v13.x);
                a2[im] = __float_as_uint(v02.y);
                a3[im] = __float_as_uint(v13.y);
            }
            #pragma unroll
            for (int jn = 0; jn < 8; jn++) {
                float2 b01 = Bp[cur][kr + t][wn + jn * 8 + g];
                unsigned b0 = __float_as_uint(b01.x);
                unsigned b1 = __float_as_uint(b01.y);
                #pragma unroll
                for (int im = 0; im < 2; im++)
                    mma_tf32(c[im][jn], a0[im], a1[im], a2[im], a3[im], b0, b1);
            }
        }
        if (have_next) {
            int nxt = cur ^ 1;
            float a0v[4] = {pa0.x, pa0.y, pa0.z, pa0.w};
            float a1v[4] = {pa1.x, pa1.y, pa1.z, pa1.w};
            #pragma unroll
            for (int q = 0; q < 4; q++) {
                Ap[nxt][fh * 4 + q][fm] = make_float2(__uint_as_float(f2tf32(a0v[q])),
                                                      __uint_as_float(f2tf32(a1v[q])));
                Bp[nxt][fh * 4 + q][fm] = make_float2(__uint_as_float(f2tf32(pbv[q])),
                                                      __uint_as_float(f2tf32(pbv[q + 4])));
            }
            __syncthreads();
            cur = nxt;
        }
    }

    #pragma unroll
    for (int im = 0; im < 2; im++) {
        #pragma unroll
        for (int half = 0; half < 2; half++) {
            int rowl = bm * 128 + wm + im * 16 + g + half * 8;
            if (rowl < cnt) {
                float* Cp = C + (size_t)rowl * N + bn * 128 + wn;
                #pragma unroll
                for (int jn = 0; jn < 8; jn++) {
                    Cp[jn * 8 + 2 * t]     = c[im][jn][half * 2 + 0];
                    Cp[jn * 8 + 2 * t + 1] = c[im][jn][half * 2 + 1];
                }
            }
        }
    }
}

// ------------------------- RoPE -------------------------
__global__ void rope_tab_k() {
    int idx = blockIdx.x * blockDim.x + threadIdx.x;
    if (idx >= SEQ * 32) return;
    int s = idx >> 5, i = idx & 31;
    double invd = pow(10000.0, -(double)(2 * i) / 64.0);
    float f = (float)s * (float)invd;     // matches reference fp32 outer product
    g_cs[2 * idx]     = (float)cos((double)f);
    g_cs[2 * idx + 1] = (float)sin((double)f);
}

__global__ void rope_k(float* __restrict__ qkv) {
    int idx = blockIdx.x * blockDim.x + threadIdx.x;
    if (idx >= TOK * NHEAD * 32) return;
    int i = idx & 31;
    int h = (idx >> 5) & 15;
    int row = idx >> 9;
    int s = row & (SEQ - 1);
    float2 cs = *(const float2*)&g_cs[2 * (s * 32 + i)];
    float c = cs.x, sn = cs.y;
    float* qp = qkv + (size_t)row * TDIM + h * 64 + 2 * i;
    float xe = qp[0], xo = qp[1];
    qp[0] = xe * c - xo * sn;
    qp[1] = xe * sn + xo * c;
    float* kp = qp + DIM;
    xe = kp[0]; xo = kp[1];
    kp[0] = xe * c - xo * sn;
    kp[1] = xe * sn + xo * c;
}

// ------------------------- flash attention, 3xTF32, raw-fp32 smem tiles (R11 proven) -------------------------
__global__ void __launch_bounds__(256, 2)
attn_k(const float* __restrict__ qkv, float* __restrict__ out) {
    extern __shared__ float sm[];
    float* Qr = sm;
    float* Kr = Qr + 64 * ATS;
    float* Vr = Kr + 64 * ATS;
    float* Pr = Vr + 64 * ATS;
    float* WMx = Pr + 64 * ATS;   // [2][64] per-half row max
    float* WSx = WMx + 128;       // [2][64] per-half row sum
    float* Mrow = WSx + 128;      // [64] running max
    float* Lrow = Mrow + 64;      // [64] running denom
    float* Arow = Lrow + 64;      // [64] alpha

    const int mt = blockIdx.x;
    const int b = blockIdx.y >> 4, h = blockIdx.y & 15;
    const int tid = threadIdx.x;
    const int warp = tid >> 5, lane = tid & 31;
    const int g = lane >> 2, t = lane & 3;
    const int wm = (warp & 3) * 16;
    const int wn = (warp >> 2) * 32;
    const int wh = warp >> 2;
    const size_t rowbase = (size_t)(b * SEQ) * TDIM;

    for (int i = tid; i < 64 * 64; i += 256) {
        int r = i >> 6, c = i & 63;
        Qr[c * ATS + r] = qkv[rowbase + (size_t)(mt * 64 + r) * TDIM + h * 64 + c];
    }
    if (tid < 64) { Mrow[tid] = -INFINITY; Lrow[tid] = 0.f; }

    const int r0 = wm + g, r1 = wm + 8 + g;
    float oc[4][4];
    #pragma unroll
    for (int j = 0; j < 4; j++)
        #pragma unroll
        for (int q = 0; q < 4; q++) oc[j][q] = 0.f;

    for (int nt = 0; nt <= mt; nt++) {
        __syncthreads();
        for (int i = tid; i < 64 * 64; i += 256) {
            int r = i >> 6, c = i & 63;
            size_t base = rowbase + (size_t)(nt * 64 + r) * TDIM + h * 64 + c;
            Kr[c * ATS + r] = qkv[base + DIM];
            Vr[r * ATS + c] = qkv[base + 2 * DIM];
        }
        __syncthreads();

        float s4[4][4];
        #pragma unroll
        for (int j = 0; j < 4; j++)
            #pragma unroll
            for (int q = 0; q < 4; q++) s4[j][q] = 0.f;
        #pragma unroll
        for (int ks = 0; ks < 64; ks += 8) {
            unsigned ah[4], al[4];
            {
                float2 hl;
                hl = hilo(Qr[(ks + t) * ATS + wm + g]);
                ah[0] = __float_as_uint(hl.x); al[0] = __float_as_uint(hl.y);
                hl = hilo(Qr[(ks + t) * ATS + wm + 8 + g]);
                ah[1] = __float_as_uint(hl.x); al[1] = __float_as_uint(hl.y);
                hl = hilo(Qr[(ks + t + 4) * ATS + wm + g]);
                ah[2] = __float_as_uint(hl.x); al[2] = __float_as_uint(hl.y);
                hl = hilo(Qr[(ks + t + 4) * ATS + wm + 8 + g]);
                ah[3] = __float_as_uint(hl.x); al[3] = __float_as_uint(hl.y);
            }
            #pragma unroll
            for (int jn = 0; jn < 4; jn++) {
                int n0 = wn + jn * 8 + g;
                float2 b0 = hilo(Kr[(ks + t) * ATS + n0]);
                float2 b1 = hilo(Kr[(ks + t + 4) * ATS + n0]);
                unsigned bh0 = __float_as_uint(b0.x), bl0 = __float_as_uint(b0.y);
                unsigned bh1 = __float_as_uint(b1.x), bl1 = __float_as_uint(b1.y);
                mma_tf32(s4[jn], ah[0], ah[1], ah[2], ah[3], bl0, bl1);
                mma_tf32(s4[jn], al[0], al[1], al[2], al[3], bh0, bh1);
                mma_tf32(s4[jn], ah[0], ah[1], ah[2], ah[3], bh0, bh1);
            }
        }

        const float scale = 0.125f;
        float mx0 = -INFINITY, mx1 = -INFINITY;
        #pragma unroll
        for (int jn = 0; jn < 4; jn++) {
            int c0 = wn + jn * 8 + 2 * t;
            float v0 = s4[jn][0] * scale;
            float v1 = s4[jn][1] * scale;
            float v2 = s4[jn][2] * scale;
            float v3 = s4[jn][3] * scale;
            if (nt == mt) {
                if (c0 > r0)     v0 = -INFINITY;
                if (c0 + 1 > r0) v1 = -INFINITY;
                if (c0 > r1)     v2 = -INFINITY;
                if (c0 + 1 > r1) v3 = -INFINITY;
            }
            s4[jn][0] = v0; s4[jn][1] = v1; s4[jn][2] = v2; s4[jn][3] = v3;
            mx0 = fmaxf(mx0, fmaxf(v0, v1));
            mx1 = fmaxf(mx1, fmaxf(v2, v3));
        }
        mx0 = fmaxf(mx0, __shfl_xor_sync(0xffffffffu, mx0, 1));
        mx0 = fmaxf(mx0, __shfl_xor_sync(0xffffffffu, mx0, 2));
        mx1 = fmaxf(mx1, __shfl_xor_sync(0xffffffffu, mx1, 1));
        mx1 = fmaxf(mx1, __shfl_xor_sync(0xffffffffu, mx1, 2));
        if (t == 0) { WMx[wh * 64 + r0] = mx0; WMx[wh * 64 + r1] = mx1; }
        __syncthreads();
        if (tid < 64) {
            float mo = Mrow[tid];
            float mn2 = fmaxf(mo, fmaxf(WMx[tid], WMx[64 + tid]));
            Arow[tid] = expf(mo - mn2);
            Mrow[tid] = mn2;
        }
        __syncthreads();

        float m0 = Mrow[r0], m1 = Mrow[r1];
        float s0 = 0.f, s1 = 0.f;
        #pragma unroll
        for (int jn = 0; jn < 4; jn++) {
            int c0 = wn + jn * 8 + 2 * t;
            float p0 = expf(s4[jn][0] - m0);
            float p1 = expf(s4[jn][1] - m0);
            float p2 = expf(s4[jn][2] - m1);
            float p3 = expf(s4[jn][3] - m1);
            s0 += p0 + p1;
            s1 += p2 + p3;
            Pr[c0 * ATS + r0] = p0;
            Pr[(c0 + 1) * ATS + r0] = p1;
            Pr[c0 * ATS + r1] = p2;
            Pr[(c0 + 1) * ATS + r1] = p3;
        }
        s0 += __shfl_xor_sync(0xffffffffu, s0, 1);
        s0 += __shfl_xor_sync(0xffffffffu, s0, 2);
        s1 += __shfl_xor_sync(0xffffffffu, s1, 1);
        s1 += __shfl_xor_sync(0xffffffffu, s1, 2);
        if (t == 0) { WSx[wh * 64 + r0] = s0; WSx[wh * 64 + r1] = s1; }
        float a0 = Arow[r0], a1 = Arow[r1];
        #pragma unroll
        for (int jn = 0; jn < 4; jn++) {
            oc[jn][0] *= a0; oc[jn][1] *= a0;
            oc[jn][2] *= a1; oc[jn][3] *= a1;
        }
        __syncthreads();
        if (tid < 64) Lrow[tid] = Lrow[tid] * Arow[tid] + WSx[tid] + WSx[64 + tid];

        #pragma unroll
        for (int ks = 0; ks < 64; ks += 8) {
            unsigned ah[4], al[4];
            {
                float2 hl;
                hl = hilo(Pr[(ks + t) * ATS + wm + g]);
                ah[0] = __float_as_uint(hl.x); al[0] = __float_as_uint(hl.y);
                hl = hilo(Pr[(ks + t) * ATS + wm + 8 + g]);
                ah[1] = __float_as_uint(hl.x); al[1] = __float_as_uint(hl.y);
                hl = hilo(Pr[(ks + t + 4) * ATS + wm + g]);
                ah[2] = __float_as_uint(hl.x); al[2] = __float_as_uint(hl.y);
                hl = hilo(Pr[(ks + t + 4) * ATS + wm + 8 + g]);
                ah[3] = __float_as_uint(hl.x); al[3] = __float_as_uint(hl.y);
            }
            #pragma unroll
            for (int jn = 0; jn < 4; jn++) {
                int n0 = wn + jn * 8 + g;
                float2 b0 = hilo(Vr[(ks + t) * ATS + n0]);
                float2 b1 = hilo(Vr[(ks + t + 4) * ATS + n0]);
                unsigned bh0 = __float_as_uint(b0.x), bl0 = __float_as_uint(b0.y);
                unsigned bh1 = __float_as_uint(b1.x), bl1 = __float_as_uint(b1.y);
                mma_tf32(oc[jn], ah[0], ah[1], ah[2], ah[3], bl0, bl1);
                mma_tf32(oc[jn], al[0], al[1], al[2], al[3], bh0, bh1);
                mma_tf32(oc[jn], ah[0], ah[1], ah[2], ah[3], bh0, bh1);
            }
        }
    }

    __syncthreads();
    float li0 = 1.f / Lrow[r0];
    float li1 = 1.f / Lrow[r1];
    int gr0 = b * SEQ + mt * 64 + r0;
    int gr1 = gr0 + 8;
    #pragma unroll
    for (int jn = 0; jn < 4; jn++) {
        int c0 = h * 64 + wn + jn * 8 + 2 * t;
        out[(size_t)gr0 * DIM + c0]     = oc[jn][0] * li0;
        out[(size_t)gr0 * DIM + c0 + 1] = oc[jn][1] * li0;
        out[(size_t)gr1 * DIM + c0]     = oc[jn][2] * li1;
        out[(size_t)gr1 * DIM + c0 + 1] = oc[jn][3] * li1;
    }
}

// ------------------------- MoE gate / routing -------------------------
__global__ void zero_k() {
    int t = threadIdx.x;
    if (t < NEXP) { g_cnt[t] = 0; g_fill[t] = 0; g_dist[t] = 0.f; }
}

__global__ void gate_k(const float* __restrict__ xn2, const float* __restrict__ gw) {
    int t = blockIdx.x;
    int wid = threadIdx.x >> 5, lane = threadIdx.x & 31;
    const float* xr = xn2 + (size_t)t * DIM;
    float acc = 0.f;
    for (int k = lane; k < DIM; k += 32) {
        float a = __bfloat162float(__float2bfloat16(xr[k]));
        float w = __bfloat162float(__float2bfloat16(gw[(size_t)k * NEXP + wid]));
        acc = fmaf(a, w, acc);
    }
    #pragma unroll
    for (int o = 16; o; o >>= 1) acc += __shfl_xor_sync(0xffffffffu, acc, o);
    __shared__ float lg[NEXP];
    if (lane == 0) lg[wid] = __bfloat162float(__float2bfloat16(acc));  // bf16 result like jax
    __syncthreads();
    if (threadIdx.x == 0) {
        float mx = lg[0];
        for (int e = 1; e < NEXP; e++) mx = fmaxf(mx, lg[e]);
        float p[NEXP], sum = 0.f;
        for (int e = 0; e < NEXP; e++) { p[e] = expf(lg[e] - mx); sum += p[e]; }
        float inv = 1.f / sum;
        for (int e = 0; e < NEXP; e++) atomicAdd(&g_dist[e], p[e] * inv);
        int i0 = 0;
        for (int e = 1; e < NEXP; e++) if (lg[e] > lg[i0]) i0 = e;
        int i1 = -1;
        for (int e = 0; e < NEXP; e++) {
            if (e == i0) continue;
            if (i1 < 0 || lg[e] > lg[i1]) i1 = e;
        }
        float eb = expf(lg[i1] - lg[i0]);
        float w0 = 1.f / (1.f + eb);
        g_cw[2 * t] = w0;
        g_cw[2 * t + 1] = eb * w0;
        g_topk[2 * t] = i0;
        g_topk[2 * t + 1] = i1;
        atomicAdd(&g_cnt[i0], 1);
        atomicAdd(&g_cnt[i1], 1);
    }
}

__global__ void offsets_k() {
    if (threadIdx.x == 0) {
        int a = 0;
        for (int e = 0; e < NEXP; e++) { g_off[e] = a; a += g_cnt[e]; }
    }
}

__global__ void fill_k() {
    int t = blockIdx.x * blockDim.x + threadIdx.x;
    if (t >= TOK) return;
    for (int k2 = 0; k2 < 2; k2++) {
        int e = g_topk[2 * t + k2];
        int pos = g_off[e] + atomicAdd(&g_fill[e], 1);
        g_perm[pos] = t;
        g_slot[2 * t + k2] = pos;
    }
}

__global__ void silu_k() {
    int i = blockIdx.x * blockDim.x + threadIdx.x;
    if (i >= SLOTS * HID) return;
    float g = g_gbuf[i], u = g_ubuf[i];
    g_gbuf[i] = g / (1.f + expf(-g)) * u;
}

__global__ void epi_k(float* __restrict__ out) {
    int i = blockIdx.x * blockDim.x + threadIdx.x;
    if (i >= TOK * DIM) return;
    int t = i >> 10, d = i & 1023;
    float r = g_x1[i];
    r += g_cw[2 * t] * g_dbuf[(size_t)g_slot[2 * t] * DIM + d];
    r += g_cw[2 * t + 1] * g_dbuf[(size_t)g_slot[2 * t + 1] * DIM + d];
    out[i] = r;
}

__global__ void fin_k(float* __restrict__ out) {
    if (threadIdx.x == 0 && blockIdx.x == 0) {
        float s = 0.f;
        for (int e = 0; e < NEXP; e++) {
            float d = g_dist[e] * (1.f / 2048.f);
            out[TOK * DIM + 1 + e] = d;
            s += d * d;
        }
        out[TOK * DIM] = 8.f * s;
    }
}

// ------------------------- launch -------------------------
extern "C" void kernel_launch(void* const* d_in, const int* in_sizes, int n_in,
                              void* d_out, int out_size) {
    const float* x    = (const float*)d_in[0];
    const float* ln1g = (const float*)d_in[1];
    const float* ln1b = (const float*)d_in[2];
    const float* ln2g = (const float*)d_in[3];
    const float* ln2b = (const float*)d_in[4];
    const float* wqkv = (const float*)d_in[5];
    const float* wo   = (const float*)d_in[6];
    const float* gw   = (const float*)d_in[7];
    const float* wg   = (const float*)d_in[8];
    const float* wu   = (const float*)d_in[9];
    const float* wd   = (const float*)d_in[10];
    float* out = (float*)d_out;

    float *pxn1, *pqkv, *pattn, *px1, *pxn2, *pg, *pu, *pd;
    cudaGetSymbolAddress((void**)&pxn1, g_xn1);
    cudaGetSymbolAddress((void**)&pqkv, g_qkv);
    cudaGetSymbolAddress((void**)&pattn, g_attn);
    cudaGetSymbolAddress((void**)&px1, g_x1);
    cudaGetSymbolAddress((void**)&pxn2, g_xn2);
    cudaGetSymbolAddress((void**)&pg, g_gbuf);
    cudaGetSymbolAddress((void**)&pu, g_ubuf);
    cudaGetSymbolAddress((void**)&pd, g_dbuf);

    const int attn_smem = (4 * 64 * ATS + 128 + 128 + 3 * 64) * (int)sizeof(float);
    cudaFuncSetAttribute(attn_k, cudaFuncAttributeMaxDynamicSharedMemorySize, attn_smem);

    zero_k<<<1, 32>>>();
    rope_tab_k<<<(SEQ * 32 + 255) / 256, 256>>>();
    ln_k<<<TOK, 256>>>(x, ln1g, ln1b, pxn1);
    gemm3x_k<<<dim3(TDIM / 128, TOK / 128), 256>>>(pxn1, wqkv, pqkv, nullptr, TDIM, DIM);
    rope_k<<<(TOK * NHEAD * 32 + 255) / 256, 256>>>(pqkv);
    attn_k<<<dim3(SEQ / 64, 4 * NHEAD), 256, attn_smem>>>(pqkv, pattn);
    gemm3x_k<<<dim3(DIM / 128, TOK / 128), 256>>>(pattn, wo, px1, x, DIM, DIM);
    ln_k<<<TOK, 256>>>(px1, ln2g, ln2b, pxn2);
    gate_k<<<TOK, 256>>>(pxn2, gw);
    offsets_k<<<1, 1>>>();
    fill_k<<<(TOK + 255) / 256, 256>>>();
    moe_mma_k<<<dim3(HID / 128, 32, NEXP), 256>>>(pxn2, wg, pg, DIM, HID, 1);
    moe_mma_k<<<dim3(HID / 128, 32, NEXP), 256>>>(pxn2, wu, pu, DIM, HID, 1);
    silu_k<<<(SLOTS * HID + 255) / 256, 256>>>();
    moe_mma_k<<<dim3(DIM / 128, 32, NEXP), 256>>>(pg, wd, pd, HID, DIM, 0);
    epi_k<<<(TOK * DIM + 255) / 256, 256>>>(out);
    fin_k<<<1, 1>>>(out);
}

// round 15
// speedup vs baseline: 1.0722x; 1.0722x over previous
#include <cuda_runtime.h>
#include <cuda_bf16.h>
#include <math.h>

#define TOK 2048
#define DIM 1024
#define TDIM 3072
#define SEQ 512
#define NHEAD 16
#define HDIM 64
#define NEXP 8
#define HID 1792
#define SLOTS 4096
#define ATS 72   // attention smem stride: 72 % 32 == 8 -> conflict-free fragment LDS

// ------------------------- scratch (device globals) -------------------------
__device__ float g_xn1[TOK * DIM];
__device__ float g_qkv[TOK * TDIM];
__device__ float g_attn[TOK * DIM];
__device__ float g_x1[TOK * DIM];
__device__ float g_xn2[TOK * DIM];
__device__ float g_gbuf[SLOTS * HID];
__device__ float g_ubuf[SLOTS * HID];
__device__ float g_dbuf[SLOTS * DIM];
__device__ float g_cw[TOK * 2];
__device__ int   g_topk[TOK * 2];
__device__ int   g_slot[TOK * 2];
__device__ int   g_perm[SLOTS];
__device__ int   g_cnt[NEXP];
__device__ int   g_off[NEXP];
__device__ int   g_fill[NEXP];
__device__ float g_dist[NEXP];
__device__ float g_cs[SEQ * 32 * 2];   // rope cos/sin table

// ------------------------- small helpers -------------------------
__device__ __forceinline__ float block_sum(float v) {
    __shared__ float red[8];
    #pragma unroll
    for (int o = 16; o; o >>= 1) v += __shfl_xor_sync(0xffffffffu, v, o);
    int w = threadIdx.x >> 5;
    if ((threadIdx.x & 31) == 0) red[w] = v;
    __syncthreads();
    if (threadIdx.x < 32) {
        float t = (threadIdx.x < 8) ? red[threadIdx.x] : 0.f;
        #pragma unroll
        for (int o = 4; o; o >>= 1) t += __shfl_xor_sync(0xffffffffu, t, o);
        if (threadIdx.x == 0) red[0] = t;
    }
    __syncthreads();
    float r = red[0];
    __syncthreads();
    return r;
}

__device__ __forceinline__ unsigned f2tf32(float x) {
    unsigned r;
    asm("cvt.rna.tf32.f32 %0, %1;" : "=r"(r) : "f"(x));
    return r;
}

__device__ __forceinline__ void mma_tf32(float* c, unsigned a0, unsigned a1,
                                         unsigned a2, unsigned a3,
                                         unsigned b0, unsigned b1) {
    asm volatile(
        "mma.sync.aligned.m16n8k8.row.col.f32.tf32.tf32.f32 "
        "{%0,%1,%2,%3}, {%4,%5,%6,%7}, {%8,%9}, {%0,%1,%2,%3};"
        : "+f"(c[0]), "+f"(c[1]), "+f"(c[2]), "+f"(c[3])
        : "r"(a0), "r"(a1), "r"(a2), "r"(a3), "r"(b0), "r"(b1));
}

__device__ __forceinline__ float2 hilo(float x) {
    float h = __uint_as_float(f2tf32(x));
    return make_float2(h, __uint_as_float(f2tf32(x - h)));
}

// ------------------------- LayerNorm -------------------------
__global__ void ln_k(const float* __restrict__ x, const float* __restrict__ g,
                     const float* __restrict__ b, float* __restrict__ y) {
    int row = blockIdx.x;
    int tid = threadIdx.x;
    const float* xr = x + (size_t)row * DIM;
    float v[4];
    float s = 0.f;
    #pragma unroll
    for (int i = 0; i < 4; i++) { v[i] = xr[tid + 256 * i]; s += v[i]; }
    float mu = block_sum(s) * (1.f / 1024.f);
    float q = 0.f;
    #pragma unroll
    for (int i = 0; i < 4; i++) { float d = v[i] - mu; q += d * d; }
    float var = block_sum(q) * (1.f / 1024.f);
    float rs = rsqrtf(var + 1e-5f);
    float* yr = y + (size_t)row * DIM;
    #pragma unroll
    for (int i = 0; i < 4; i++) {
        int c = tid + 256 * i;
        yr[c] = (v[i] - mu) * rs * g[c] + b[c];
    }
}

// ------------------------- dense 3xTF32 GEMM, k-paired float2 smem (R14 proven) -------------------------
__global__ void __launch_bounds__(256, 2)
gemm3x_k(const float* __restrict__ A, const float* __restrict__ B,
         float* __restrict__ C, const float* __restrict__ R, int N, int K) {
    const int bn = blockIdx.x, bm = blockIdx.y;
    __shared__ float2 Ap[8][132];
    __shared__ float2 Bp[8][132];

    const int tid = threadIdx.x;
    const int warp = tid >> 5, lane = tid & 31;
    const int g = lane >> 2, t = lane & 3;
    const int wm = (warp & 3) * 32;
    const int wn = (warp >> 2) * 64;

    const int fm = tid & 127;
    const int fh = tid >> 7;
    const float* fap = A + (size_t)(bm * 128 + fm) * K + fh * 8;
    const float* fbp = B + (size_t)(fh * 8) * N + bn * 128 + fm;

    float c[2][8][4];
    #pragma unroll
    for (int im = 0; im < 2; im++)
        #pragma unroll
        for (int jn = 0; jn < 8; jn++)
            #pragma unroll
            for (int q = 0; q < 4; q++) c[im][jn][q] = 0.f;

    float4 pa0, pa1;
    float pbv[8];
    pa0 = *(const float4*)(fap);
    pa1 = *(const float4*)(fap + 4);
    #pragma unroll
    for (int j = 0; j < 8; j++) pbv[j] = fbp[(size_t)j * N];
    {
        float a0v[4] = {pa0.x, pa0.y, pa0.z, pa0.w};
        float a1v[4] = {pa1.x, pa1.y, pa1.z, pa1.w};
        #pragma unroll
        for (int q = 0; q < 4; q++) {
            Ap[fh * 4 + q][fm] = make_float2(a0v[q], a1v[q]);
            Bp[fh * 4 + q][fm] = make_float2(pbv[q], pbv[q + 4]);
        }
    }
    __syncthreads();

    const int ntiles = K / 16;
    for (int kt = 0; kt < ntiles; kt++) {
        const bool have_next = (kt + 1) < ntiles;
        if (have_next) {
            pa0 = *(const float4*)(fap + (kt + 1) * 16);
            pa1 = *(const float4*)(fap + (kt + 1) * 16 + 4);
            #pragma unroll
            for (int j = 0; j < 8; j++)
                pbv[j] = fbp[(size_t)((kt + 1) * 16 + j) * N];
        }
        #pragma unroll
        for (int ks = 0; ks < 16; ks += 8) {
            const int kr = ks >> 1;   // 0 or 4
            unsigned ah[2][4], al[2][4];
            #pragma unroll
            for (int im = 0; im < 2; im++) {
                int m0 = wm + im * 16 + g;
                float2 v02 = Ap[kr + t][m0];
                float2 v13 = Ap[kr + t][m0 + 8];
                float2 hl;
                hl = hilo(v02.x); ah[im][0] = __float_as_uint(hl.x); al[im][0] = __float_as_uint(hl.y);
                hl = hilo(v13.x); ah[im][1] = __float_as_uint(hl.x); al[im][1] = __float_as_uint(hl.y);
                hl = hilo(v02.y); ah[im][2] = __float_as_uint(hl.x); al[im][2] = __float_as_uint(hl.y);
                hl = hilo(v13.y); ah[im][3] = __float_as_uint(hl.x); al[im][3] = __float_as_uint(hl.y);
            }
            #pragma unroll
            for (int jn = 0; jn < 8; jn++) {
                int n0 = wn + jn * 8 + g;
                float2 braw = Bp[kr + t][n0];
                float2 b0 = hilo(braw.x);
                float2 b1 = hilo(braw.y);
                unsigned bh0 = __float_as_uint(b0.x), bl0 = __float_as_uint(b0.y);
                unsigned bh1 = __float_as_uint(b1.x), bl1 = __float_as_uint(b1.y);
                #pragma unroll
                for (int im = 0; im < 2; im++) {
                    mma_tf32(c[im][jn], ah[im][0], ah[im][1], ah[im][2], ah[im][3], bl0, bl1);
                    mma_tf32(c[im][jn], al[im][0], al[im][1], al[im][2], al[im][3], bh0, bh1);
                    mma_tf32(c[im][jn], ah[im][0], ah[im][1], ah[im][2], ah[im][3], bh0, bh1);
                }
            }
        }
        if (have_next) {
            __syncthreads();
            float a0v[4] = {pa0.x, pa0.y, pa0.z, pa0.w};
            float a1v[4] = {pa1.x, pa1.y, pa1.z, pa1.w};
            #pragma unroll
            for (int q = 0; q < 4; q++) {
                Ap[fh * 4 + q][fm] = make_float2(a0v[q], a1v[q]);
                Bp[fh * 4 + q][fm] = make_float2(pbv[q], pbv[q + 4]);
            }
            __syncthreads();
        }
    }

    #pragma unroll
    for (int im = 0; im < 2; im++) {
        #pragma unroll
        for (int half = 0; half < 2; half++) {
            int row = bm * 128 + wm + im * 16 + g + half * 8;
            float* Cp = C + (size_t)row * N + bn * 128 + wn;
            if (R) {
                const float* Rp = R + (size_t)row * N + bn * 128 + wn;
                #pragma unroll
                for (int jn = 0; jn < 8; jn++) {
                    Cp[jn * 8 + 2 * t]     = c[im][jn][half * 2 + 0] + Rp[jn * 8 + 2 * t];
                    Cp[jn * 8 + 2 * t + 1] = c[im][jn][half * 2 + 1] + Rp[jn * 8 + 2 * t + 1];
                }
            } else {
                #pragma unroll
                for (int jn = 0; jn < 8; jn++) {
                    Cp[jn * 8 + 2 * t]     = c[im][jn][half * 2 + 0];
                    Cp[jn * 8 + 2 * t + 1] = c[im][jn][half * 2 + 1];
                }
            }
        }
    }
}

// ------------------------- MoE grouped GEMM, TF32 tensor cores (R11/R13 proven) -------------------------
__global__ void __launch_bounds__(256, 2)
moe_mma_k(const float* __restrict__ X, const float* __restrict__ W,
          float* __restrict__ Cb, int K, int N, int gather) {
    const int e = blockIdx.z;
    const int cnt = g_cnt[e];
    const int bm = blockIdx.y;
    if (bm * 128 >= cnt) return;
    const int off = g_off[e];
    const int bn = blockIdx.x;
    const float* B = W + (size_t)e * K * N;
    float* C = Cb + (size_t)off * N;

    __shared__ float As[2][16][136];
    __shared__ float Bs[2][16][136];

    const int tid = threadIdx.x;
    const int warp = tid >> 5, lane = tid & 31;
    const int g = lane >> 2, t = lane & 3;
    const int wm = (warp & 3) * 32;
    const int wn = (warp >> 2) * 64;

    int amrow[2]; const float* aptr[2]; bool avalid[2];
    int akq[2];
    #pragma unroll
    for (int i = 0; i < 2; i++) {
        int task = tid + 256 * i;
        int mr = task >> 2;
        akq[i] = (task & 3) * 4;
        amrow[i] = mr;
        avalid[i] = (bm * 128 + mr) < cnt;
        int slot = off + bm * 128 + (avalid[i] ? mr : 0);
        int arow = gather ? g_perm[slot] : slot;
        aptr[i] = X + (size_t)arow * K + akq[i];
    }
    int bkr[2], bnq[2]; const float* bptr[2];
    #pragma unroll
    for (int i = 0; i < 2; i++) {
        int task = tid + 256 * i;
        bkr[i] = task >> 5;
        bnq[i] = (task & 31) * 4;
        bptr[i] = B + (size_t)bkr[i] * N + bn * 128 + bnq[i];
    }

    float c[2][8][4];
    #pragma unroll
    for (int im = 0; im < 2; im++)
        #pragma unroll
        for (int jn = 0; jn < 8; jn++)
            #pragma unroll
            for (int q = 0; q < 4; q++) c[im][jn][q] = 0.f;

    const int ntiles = K / 16;

    #pragma unroll
    for (int i = 0; i < 2; i++) {
        float4 av = avalid[i] ? *(const float4*)(aptr[i]) : make_float4(0, 0, 0, 0);
        As[0][akq[i] + 0][amrow[i]] = __uint_as_float(f2tf32(av.x));
        As[0][akq[i] + 1][amrow[i]] = __uint_as_float(f2tf32(av.y));
        As[0][akq[i] + 2][amrow[i]] = __uint_as_float(f2tf32(av.z));
        As[0][akq[i] + 3][amrow[i]] = __uint_as_float(f2tf32(av.w));
        float4 bv = *(const float4*)(bptr[i]);
        Bs[0][bkr[i]][bnq[i] + 0] = __uint_as_float(f2tf32(bv.x));
        Bs[0][bkr[i]][bnq[i] + 1] = __uint_as_float(f2tf32(bv.y));
        Bs[0][bkr[i]][bnq[i] + 2] = __uint_as_float(f2tf32(bv.z));
        Bs[0][bkr[i]][bnq[i] + 3] = __uint_as_float(f2tf32(bv.w));
    }
    __syncthreads();

    int cur = 0;
    for (int kt = 0; kt < ntiles; kt++) {
        float4 pa[2], pb[2];
        bool have_next = (kt + 1) < ntiles;
        if (have_next) {
            #pragma unroll
            for (int i = 0; i < 2; i++) {
                pa[i] = avalid[i] ? *(const float4*)(aptr[i] + (kt + 1) * 16)
                                  : make_float4(0, 0, 0, 0);
                pb[i] = *(const float4*)(bptr[i] + (size_t)(kt + 1) * 16 * N);
            }
        }
        #pragma unroll
        for (int ks = 0; ks < 16; ks += 8) {
            unsigned a0[2], a1[2], a2[2], a3[2];
            #pragma unroll
            for (int im = 0; im < 2; im++) {
                a0[im] = __float_as_uint(As[cur][ks + t][wm + im * 16 + g]);
                a1[im] = __float_as_uint(As[cur][ks + t][wm + im * 16 + 8 + g]);
                a2[im] = __float_as_uint(As[cur][ks + t + 4][wm + im * 16 + g]);
                a3[im] = __float_as_uint(As[cur][ks + t + 4][wm + im * 16 + 8 + g]);
            }
            #pragma unroll
            for (int jn = 0; jn < 8; jn++) {
                unsigned b0 = __float_as_uint(Bs[cur][ks + t][wn + jn * 8 + g]);
                unsigned b1 = __float_as_uint(Bs[cur][ks + t + 4][wn + jn * 8 + g]);
                #pragma unroll
                for (int im = 0; im < 2; im++)
                    mma_tf32(c[im][jn], a0[im], a1[im], a2[im], a3[im], b0, b1);
            }
        }
        if (have_next) {
            int nxt = cur ^ 1;
            #pragma unroll
            for (int i = 0; i < 2; i++) {
                As[nxt][akq[i] + 0][amrow[i]] = __uint_as_float(f2tf32(pa[i].x));
                As[nxt][akq[i] + 1][amrow[i]] = __uint_as_float(f2tf32(pa[i].y));
                As[nxt][akq[i] + 2][amrow[i]] = __uint_as_float(f2tf32(pa[i].z));
                As[nxt][akq[i] + 3][amrow[i]] = __uint_as_float(f2tf32(pa[i].w));
                Bs[nxt][bkr[i]][bnq[i] + 0] = __uint_as_float(f2tf32(pb[i].x));
                Bs[nxt][bkr[i]][bnq[i] + 1] = __uint_as_float(f2tf32(pb[i].y));
                Bs[nxt][bkr[i]][bnq[i] + 2] = __uint_as_float(f2tf32(pb[i].z));
                Bs[nxt][bkr[i]][bnq[i] + 3] = __uint_as_float(f2tf32(pb[i].w));
            }
            __syncthreads();
            cur = nxt;
        }
    }

    #pragma unroll
    for (int im = 0; im < 2; im++) {
        #pragma unroll
        for (int half = 0; half < 2; half++) {
            int rowl = bm * 128 + wm + im * 16 + g + half * 8;
            if (rowl < cnt) {
                float* Cp = C + (size_t)rowl * N + bn * 128 + wn;
                #pragma unroll
                for (int jn = 0; jn < 8; jn++) {
                    Cp[jn * 8 + 2 * t]     = c[im][jn][half * 2 + 0];
                    Cp[jn * 8 + 2 * t + 1] = c[im][jn][half * 2 + 1];
                }
            }
        }
    }
}

// ------------------------- RoPE -------------------------
__global__ void rope_tab_k() {
    int idx = blockIdx.x * blockDim.x + threadIdx.x;
    if (idx >= SEQ * 32) return;
    int s = idx >> 5, i = idx & 31;
    double invd = pow(10000.0, -(double)(2 * i) / 64.0);
    float f = (float)s * (float)invd;     // matches reference fp32 outer product
    g_cs[2 * idx]     = (float)cos((double)f);
    g_cs[2 * idx + 1] = (float)sin((double)f);
}

__global__ void rope_k(float* __restrict__ qkv) {
    int idx = blockIdx.x * blockDim.x + threadIdx.x;
    if (idx >= TOK * NHEAD * 32) return;
    int i = idx & 31;
    int h = (idx >> 5) & 15;
    int row = idx >> 9;
    int s = row & (SEQ - 1);
    float2 cs = *(const float2*)&g_cs[2 * (s * 32 + i)];
    float c = cs.x, sn = cs.y;
    float* qp = qkv + (size_t)row * TDIM + h * 64 + 2 * i;
    float xe = qp[0], xo = qp[1];
    qp[0] = xe * c - xo * sn;
    qp[1] = xe * sn + xo * c;
    float* kp = qp + DIM;
    xe = kp[0]; xo = kp[1];
    kp[0] = xe * c - xo * sn;
    kp[1] = xe * sn + xo * c;
}

// ------------------------- flash attention, 3xTF32, raw-fp32 smem tiles (R11 proven) -------------------------
__global__ void __launch_bounds__(256, 2)
attn_k(const float* __restrict__ qkv, float* __restrict__ out) {
    extern __shared__ float sm[];
    float* Qr = sm;
    float* Kr = Qr + 64 * ATS;
    float* Vr = Kr + 64 * ATS;
    float* Pr = Vr + 64 * ATS;
    float* WMx = Pr + 64 * ATS;   // [2][64] per-half row max
    float* WSx = WMx + 128;       // [2][64] per-half row sum
    float* Mrow = WSx + 128;      // [64] running max
    float* Lrow = Mrow + 64;      // [64] running denom
    float* Arow = Lrow + 64;      // [64] alpha

    const int mt = blockIdx.x;
    const int b = blockIdx.y >> 4, h = blockIdx.y & 15;
    const int tid = threadIdx.x;
    const int warp = tid >> 5, lane = tid & 31;
    const int g = lane >> 2, t = lane & 3;
    const int wm = (warp & 3) * 16;
    const int wn = (warp >> 2) * 32;
    const int wh = warp >> 2;
    const size_t rowbase = (size_t)(b * SEQ) * TDIM;

    for (int i = tid; i < 64 * 64; i += 256) {
        int r = i >> 6, c = i & 63;
        Qr[c * ATS + r] = qkv[rowbase + (size_t)(mt * 64 + r) * TDIM + h * 64 + c];
    }
    if (tid < 64) { Mrow[tid] = -INFINITY; Lrow[tid] = 0.f; }

    const int r0 = wm + g, r1 = wm + 8 + g;
    float oc[4][4];
    #pragma unroll
    for (int j = 0; j < 4; j++)
        #pragma unroll
        for (int q = 0; q < 4; q++) oc[j][q] = 0.f;

    for (int nt = 0; nt <= mt; nt++) {
        __syncthreads();
        for (int i = tid; i < 64 * 64; i += 256) {
            int r = i >> 6, c = i & 63;
            size_t base = rowbase + (size_t)(nt * 64 + r) * TDIM + h * 64 + c;
            Kr[c * ATS + r] = qkv[base + DIM];
            Vr[r * ATS + c] = qkv[base + 2 * DIM];
        }
        __syncthreads();

        float s4[4][4];
        #pragma unroll
        for (int j = 0; j < 4; j++)
            #pragma unroll
            for (int q = 0; q < 4; q++) s4[j][q] = 0.f;
        #pragma unroll
        for (int ks = 0; ks < 64; ks += 8) {
            unsigned ah[4], al[4];
            {
                float2 hl;
                hl = hilo(Qr[(ks + t) * ATS + wm + g]);
                ah[0] = __float_as_uint(hl.x); al[0] = __float_as_uint(hl.y);
                hl = hilo(Qr[(ks + t) * ATS + wm + 8 + g]);
                ah[1] = __float_as_uint(hl.x); al[1] = __float_as_uint(hl.y);
                hl = hilo(Qr[(ks + t + 4) * ATS + wm + g]);
                ah[2] = __float_as_uint(hl.x); al[2] = __float_as_uint(hl.y);
                hl = hilo(Qr[(ks + t + 4) * ATS + wm + 8 + g]);
                ah[3] = __float_as_uint(hl.x); al[3] = __float_as_uint(hl.y);
            }
            #pragma unroll
            for (int jn = 0; jn < 4; jn++) {
                int n0 = wn + jn * 8 + g;
                float2 b0 = hilo(Kr[(ks + t) * ATS + n0]);
                float2 b1 = hilo(Kr[(ks + t + 4) * ATS + n0]);
                unsigned bh0 = __float_as_uint(b0.x), bl0 = __float_as_uint(b0.y);
                unsigned bh1 = __float_as_uint(b1.x), bl1 = __float_as_uint(b1.y);
                mma_tf32(s4[jn], ah[0], ah[1], ah[2], ah[3], bl0, bl1);
                mma_tf32(s4[jn], al[0], al[1], al[2], al[3], bh0, bh1);
                mma_tf32(s4[jn], ah[0], ah[1], ah[2], ah[3], bh0, bh1);
            }
        }

        const float scale = 0.125f;
        float mx0 = -INFINITY, mx1 = -INFINITY;
        #pragma unroll
        for (int jn = 0; jn < 4; jn++) {
            int c0 = wn + jn * 8 + 2 * t;
            float v0 = s4[jn][0] * scale;
            float v1 = s4[jn][1] * scale;
            float v2 = s4[jn][2] * scale;
            float v3 = s4[jn][3] * scale;
            if (nt == mt) {
                if (c0 > r0)     v0 = -INFINITY;
                if (c0 + 1 > r0) v1 = -INFINITY;
                if (c0 > r1)     v2 = -INFINITY;
                if (c0 + 1 > r1) v3 = -INFINITY;
            }
            s4[jn][0] = v0; s4[jn][1] = v1; s4[jn][2] = v2; s4[jn][3] = v3;
            mx0 = fmaxf(mx0, fmaxf(v0, v1));
            mx1 = fmaxf(mx1, fmaxf(v2, v3));
        }
        mx0 = fmaxf(mx0, __shfl_xor_sync(0xffffffffu, mx0, 1));
        mx0 = fmaxf(mx0, __shfl_xor_sync(0xffffffffu, mx0, 2));
        mx1 = fmaxf(mx1, __shfl_xor_sync(0xffffffffu, mx1, 1));
        mx1 = fmaxf(mx1, __shfl_xor_sync(0xffffffffu, mx1, 2));
        if (t == 0) { WMx[wh * 64 + r0] = mx0; WMx[wh * 64 + r1] = mx1; }
        __syncthreads();
        if (tid < 64) {
            float mo = Mrow[tid];
            float mn2 = fmaxf(mo, fmaxf(WMx[tid], WMx[64 + tid]));
            Arow[tid] = expf(mo - mn2);
            Mrow[tid] = mn2;
        }
        __syncthreads();

        float m0 = Mrow[r0], m1 = Mrow[r1];
        float s0 = 0.f, s1 = 0.f;
        #pragma unroll
        for (int jn = 0; jn < 4; jn++) {
            int c0 = wn + jn * 8 + 2 * t;
            float p0 = expf(s4[jn][0] - m0);
            float p1 = expf(s4[jn][1] - m0);
            float p2 = expf(s4[jn][2] - m1);
            float p3 = expf(s4[jn][3] - m1);
            s0 += p0 + p1;
            s1 += p2 + p3;
            Pr[c0 * ATS + r0] = p0;
            Pr[(c0 + 1) * ATS + r0] = p1;
            Pr[c0 * ATS + r1] = p2;
            Pr[(c0 + 1) * ATS + r1] = p3;
        }
        s0 += __shfl_xor_sync(0xffffffffu, s0, 1);
        s0 += __shfl_xor_sync(0xffffffffu, s0, 2);
        s1 += __shfl_xor_sync(0xffffffffu, s1, 1);
        s1 += __shfl_xor_sync(0xffffffffu, s1, 2);
        if (t == 0) { WSx[wh * 64 + r0] = s0; WSx[wh * 64 + r1] = s1; }
        float a0 = Arow[r0], a1 = Arow[r1];
        #pragma unroll
        for (int jn = 0; jn < 4; jn++) {
            oc[jn][0] *= a0; oc[jn][1] *= a0;
            oc[jn][2] *= a1; oc[jn][3] *= a1;
        }
        __syncthreads();
        if (tid < 64) Lrow[tid] = Lrow[tid] * Arow[tid] + WSx[tid] + WSx[64 + tid];

        #pragma unroll
        for (int ks = 0; ks < 64; ks += 8) {
            unsigned ah[4], al[4];
            {
                float2 hl;
                hl = hilo(Pr[(ks + t) * ATS + wm + g]);
                ah[0] = __float_as_uint(hl.x); al[0] = __float_as_uint(hl.y);
                hl = hilo(Pr[(ks + t) * ATS + wm + 8 + g]);
                ah[1] = __float_as_uint(hl.x); al[1] = __float_as_uint(hl.y);
                hl = hilo(Pr[(ks + t + 4) * ATS + wm + g]);
                ah[2] = __float_as_uint(hl.x); al[2] = __float_as_uint(hl.y);
                hl = hilo(Pr[(ks + t + 4) * ATS + wm + 8 + g]);
                ah[3] = __float_as_uint(hl.x); al[3] = __float_as_uint(hl.y);
            }
            #pragma unroll
            for (int jn = 0; jn < 4; jn++) {
                int n0 = wn + jn * 8 + g;
                float2 b0 = hilo(Vr[(ks + t) * ATS + n0]);
                float2 b1 = hilo(Vr[(ks + t + 4) * ATS + n0]);
                unsigned bh0 = __float_as_uint(b0.x), bl0 = __float_as_uint(b0.y);
                unsigned bh1 = __float_as_uint(b1.x), bl1 = __float_as_uint(b1.y);
                mma_tf32(oc[jn], ah[0], ah[1], ah[2], ah[3], bl0, bl1);
                mma_tf32(oc[jn], al[0], al[1], al[2], al[3], bh0, bh1);
                mma_tf32(oc[jn], ah[0], ah[1], ah[2], ah[3], bh0, bh1);
            }
        }
    }

    __syncthreads();
    float li0 = 1.f / Lrow[r0];
    float li1 = 1.f / Lrow[r1];
    int gr0 = b * SEQ + mt * 64 + r0;
    int gr1 = gr0 + 8;
    #pragma unroll
    for (int jn = 0; jn < 4; jn++) {
        int c0 = h * 64 + wn + jn * 8 + 2 * t;
        out[(size_t)gr0 * DIM + c0]     = oc[jn][0] * li0;
        out[(size_t)gr0 * DIM + c0 + 1] = oc[jn][1] * li0;
        out[(size_t)gr1 * DIM + c0]     = oc[jn][2] * li1;
        out[(size_t)gr1 * DIM + c0 + 1] = oc[jn][3] * li1;
    }
}

// ------------------------- MoE gate / routing -------------------------
__global__ void zero_k() {
    int t = threadIdx.x;
    if (t < NEXP) { g_cnt[t] = 0; g_fill[t] = 0; g_dist[t] = 0.f; }
}

__global__ void gate_k(const float* __restrict__ xn2, const float* __restrict__ gw) {
    int t = blockIdx.x;
    int wid = threadIdx.x >> 5, lane = threadIdx.x & 31;
    const float* xr = xn2 + (size_t)t * DIM;
    float acc = 0.f;
    for (int k = lane; k < DIM; k += 32) {
        float a = __bfloat162float(__float2bfloat16(xr[k]));
        float w = __bfloat162float(__float2bfloat16(gw[(size_t)k * NEXP + wid]));
        acc = fmaf(a, w, acc);
    }
    #pragma unroll
    for (int o = 16; o; o >>= 1) acc += __shfl_xor_sync(0xffffffffu, acc, o);
    __shared__ float lg[NEXP];
    if (lane == 0) lg[wid] = __bfloat162float(__float2bfloat16(acc));  // bf16 result like jax
    __syncthreads();
    if (threadIdx.x == 0) {
        float mx = lg[0];
        for (int e = 1; e < NEXP; e++) mx = fmaxf(mx, lg[e]);
        float p[NEXP], sum = 0.f;
        for (int e = 0; e < NEXP; e++) { p[e] = expf(lg[e] - mx); sum += p[e]; }
        float inv = 1.f / sum;
        for (int e = 0; e < NEXP; e++) atomicAdd(&g_dist[e], p[e] * inv);
        int i0 = 0;
        for (int e = 1; e < NEXP; e++) if (lg[e] > lg[i0]) i0 = e;
        int i1 = -1;
        for (int e = 0; e < NEXP; e++) {
            if (e == i0) continue;
            if (i1 < 0 || lg[e] > lg[i1]) i1 = e;
        }
        float eb = expf(lg[i1] - lg[i0]);
        float w0 = 1.f / (1.f + eb);
        g_cw[2 * t] = w0;
        g_cw[2 * t + 1] = eb * w0;
        g_topk[2 * t] = i0;
        g_topk[2 * t + 1] = i1;
        atomicAdd(&g_cnt[i0], 1);
        atomicAdd(&g_cnt[i1], 1);
    }
}

__global__ void offsets_k() {
    if (threadIdx.x == 0) {
        int a = 0;
        for (int e = 0; e < NEXP; e++) { g_off[e] = a; a += g_cnt[e]; }
    }
}

__global__ void fill_k() {
    int t = blockIdx.x * blockDim.x + threadIdx.x;
    if (t >= TOK) return;
    for (int k2 = 0; k2 < 2; k2++) {
        int e = g_topk[2 * t + k2];
        int pos = g_off[e] + atomicAdd(&g_fill[e], 1);
        g_perm[pos] = t;
        g_slot[2 * t + k2] = pos;
    }
}

__global__ void silu_k() {
    int i = blockIdx.x * blockDim.x + threadIdx.x;
    if (i >= SLOTS * HID) return;
    float g = g_gbuf[i], u = g_ubuf[i];
    g_gbuf[i] = g / (1.f + expf(-g)) * u;
}

__global__ void epi_k(float* __restrict__ out) {
    int i = blockIdx.x * blockDim.x + threadIdx.x;
    if (i >= TOK * DIM) return;
    int t = i >> 10, d = i & 1023;
    float r = g_x1[i];
    r += g_cw[2 * t] * g_dbuf[(size_t)g_slot[2 * t] * DIM + d];
    r += g_cw[2 * t + 1] * g_dbuf[(size_t)g_slot[2 * t + 1] * DIM + d];
    out[i] = r;
}

__global__ void fin_k(float* __restrict__ out) {
    if (threadIdx.x == 0 && blockIdx.x == 0) {
        float s = 0.f;
        for (int e = 0; e < NEXP; e++) {
            float d = g_dist[e] * (1.f / 2048.f);
            out[TOK * DIM + 1 + e] = d;
            s += d * d;
        }
        out[TOK * DIM] = 8.f * s;
    }
}

// ------------------------- launch -------------------------
extern "C" void kernel_launch(void* const* d_in, const int* in_sizes, int n_in,
                              void* d_out, int out_size) {
    const float* x    = (const float*)d_in[0];
    const float* ln1g = (const float*)d_in[1];
    const float* ln1b = (const float*)d_in[2];
    const float* ln2g = (const float*)d_in[3];
    const float* ln2b = (const float*)d_in[4];
    const float* wqkv = (const float*)d_in[5];
    const float* wo   = (const float*)d_in[6];
    const float* gw   = (const float*)d_in[7];
    const float* wg   = (const float*)d_in[8];
    const float* wu   = (const float*)d_in[9];
    const float* wd   = (const float*)d_in[10];
    float* out = (float*)d_out;

    float *pxn1, *pqkv, *pattn, *px1, *pxn2, *pg, *pu, *pd;
    cudaGetSymbolAddress((void**)&pxn1, g_xn1);
    cudaGetSymbolAddress((void**)&pqkv, g_qkv);
    cudaGetSymbolAddress((void**)&pattn, g_attn);
    cudaGetSymbolAddress((void**)&px1, g_x1);
    cudaGetSymbolAddress((void**)&pxn2, g_xn2);
    cudaGetSymbolAddress((void**)&pg, g_gbuf);
    cudaGetSymbolAddress((void**)&pu, g_ubuf);
    cudaGetSymbolAddress((void**)&pd, g_dbuf);

    const int attn_smem = (4 * 64 * ATS + 128 + 128 + 3 * 64) * (int)sizeof(float);
    cudaFuncSetAttribute(attn_k, cudaFuncAttributeMaxDynamicSharedMemorySize, attn_smem);

    zero_k<<<1, 32>>>();
    rope_tab_k<<<(SEQ * 32 + 255) / 256, 256>>>();
    ln_k<<<TOK, 256>>>(x, ln1g, ln1b, pxn1);
    gemm3x_k<<<dim3(TDIM / 128, TOK / 128), 256>>>(pxn1, wqkv, pqkv, nullptr, TDIM, DIM);
    rope_k<<<(TOK * NHEAD * 32 + 255) / 256, 256>>>(pqkv);
    attn_k<<<dim3(SEQ / 64, 4 * NHEAD), 256, attn_smem>>>(pqkv, pattn);
    gemm3x_k<<<dim3(DIM / 128, TOK / 128), 256>>>(pattn, wo, px1, x, DIM, DIM);
    ln_k<<<TOK, 256>>>(px1, ln2g, ln2b, pxn2);
    gate_k<<<TOK, 256>>>(pxn2, gw);
    offsets_k<<<1, 1>>>();
    fill_k<<<(TOK + 255) / 256, 256>>>();
    moe_mma_k<<<dim3(HID / 128, 32, NEXP), 256>>>(pxn2, wg, pg, DIM, HID, 1);
    moe_mma_k<<<dim3(HID / 128, 32, NEXP), 256>>>(pxn2, wu, pu, DIM, HID, 1);
    silu_k<<<(SLOTS * HID + 255) / 256, 256>>>();
    moe_mma_k<<<dim3(DIM / 128, 32, NEXP), 256>>>(pg, wd, pd, HID, DIM, 0);
    epi_k<<<(TOK * DIM + 255) / 256, 256>>>(out);
    fin_k<<<1, 1>>>(out);
}